// round 11
// baseline (speedup 1.0000x reference)
#include <cuda_runtime.h>
#include <math_constants.h>

// x: (64, 4096, 256) fp32; top-8 over axis 1 (S), sorted desc -> (64, 8, 256)
#define B_DIM 64
#define S_DIM 4096
#define C_DIM 256
#define K_TOP 8

#define CHUNKS 16
#define CHUNK_S (S_DIM / CHUNKS)        // 256
#define PAIRS_PER_BLOCK 2               // 256 threads = 2 (b,chunk) pairs x 128 lanes
#define GRID1 (B_DIM * CHUNKS / PAIRS_PER_BLOCK)  // 512 blocks

typedef unsigned long long u64;

// Partials, layout [b][c][chunk][k]: 8 MiB static scratch, 256B-aligned.
// Each (b,c,chunk) record is 8 floats = 32B (v4.b64 granularity).
__device__ __align__(256) float g_partial[B_DIM * C_DIM * CHUNKS * K_TOP];

// ---- L2 residency control (v4.b64 = 32B, the only width ptxas accepts) ----
__device__ __forceinline__ u64 pk2(float lo, float hi) {
    return (u64)__float_as_uint(lo) | ((u64)__float_as_uint(hi) << 32);
}
__device__ __forceinline__ float ulo(u64 v) {
    return __uint_as_float((unsigned)(v & 0xFFFFFFFFu));
}
__device__ __forceinline__ float uhi(u64 v) {
    return __uint_as_float((unsigned)(v >> 32));
}
// Store 32B (8 sorted floats) with evict_last (pin behind the input stream).
__device__ __forceinline__ void st_evl_32(float* p, const float (&t)[8]) {
    u64 a = pk2(t[0], t[1]), b = pk2(t[2], t[3]);
    u64 c = pk2(t[4], t[5]), d = pk2(t[6], t[7]);
    asm volatile("st.global.L2::evict_last.v4.b64 [%0], {%1,%2,%3,%4};"
                 :: "l"(p), "l"(a), "l"(b), "l"(c), "l"(d) : "memory");
}
// Load 32B (8 floats) with evict_first (read-once).
__device__ __forceinline__ void ld_evf_32(const float* p, float (&t)[8]) {
    u64 a, b, c, d;
    asm volatile("ld.global.L2::evict_first.v4.b64 {%0,%1,%2,%3}, [%4];"
                 : "=l"(a), "=l"(b), "=l"(c), "=l"(d) : "l"(p));
    t[0] = ulo(a); t[1] = uhi(a); t[2] = ulo(b); t[3] = uhi(b);
    t[4] = ulo(c); t[5] = uhi(c); t[6] = ulo(d); t[7] = uhi(d);
}

// Compare-exchange keeping max at 'a' (descending order).
__device__ __forceinline__ void ce(float& a, float& b) {
    float hi = fmaxf(a, b);
    float lo = fminf(a, b);
    a = hi; b = lo;
}

// Batcher odd-even mergesort, n=8, 19 CE, descending.
__device__ __forceinline__ void sort8_desc(float (&f)[8]) {
    ce(f[0],f[1]); ce(f[2],f[3]); ce(f[4],f[5]); ce(f[6],f[7]);
    ce(f[0],f[2]); ce(f[1],f[3]); ce(f[4],f[6]); ce(f[5],f[7]);
    ce(f[1],f[2]); ce(f[5],f[6]);
    ce(f[0],f[4]); ce(f[1],f[5]); ce(f[2],f[6]); ce(f[3],f[7]);
    ce(f[2],f[4]); ce(f[3],f[5]);
    ce(f[1],f[2]); ce(f[3],f[4]); ce(f[5],f[6]);
}

// Exact sorted top-8 of the union of two descending-sorted 8-lists.
__device__ __forceinline__ void merge8_desc(float (&t)[8], const float (&g)[8]) {
    #pragma unroll
    for (int i = 0; i < 8; ++i) t[i] = fmaxf(t[i], g[7 - i]);
    ce(t[0],t[4]); ce(t[1],t[5]); ce(t[2],t[6]); ce(t[3],t[7]);
    ce(t[0],t[2]); ce(t[1],t[3]); ce(t[4],t[6]); ce(t[5],t[7]);
    ce(t[0],t[1]); ce(t[2],t[3]); ce(t[4],t[5]); ce(t[6],t[7]);
}

// Pass 1 (R8-proven config): block = 2 (batch,chunk) pairs; 128 lanes x
// float2 = 256 channels; 16 batched LDG.64 per iteration.
__global__ __launch_bounds__(256, 3) void kmax_partial_kernel(
    const float2* __restrict__ x2)
{
    const int sub  = threadIdx.x >> 7;          // 0..1
    const int lane = threadIdx.x & 127;         // float2 channel group
    const int pair = blockIdx.x * PAIRS_PER_BLOCK + sub;
    const int batch = pair >> 4;                // / CHUNKS
    const int chunk = pair & (CHUNKS - 1);

    const float2* __restrict__ p =
        x2 + ((size_t)batch * S_DIM + (size_t)chunk * CHUNK_S) * (C_DIM / 2) + lane;

    float t0[8], t1[8];
    #pragma unroll
    for (int i = 0; i < 8; ++i) { t0[i] = -CUDART_INF_F; t1[i] = -CUDART_INF_F; }

    #pragma unroll 1
    for (int s = 0; s < CHUNK_S; s += 16) {
        float2 buf[16];
        #pragma unroll
        for (int u = 0; u < 16; ++u)
            buf[u] = __ldcs(p + (size_t)(s + u) * (C_DIM / 2));

        float f[8], g[8];
        // channel .x
        #pragma unroll
        for (int u = 0; u < 8; ++u) { f[u] = buf[u].x; g[u] = buf[u + 8].x; }
        sort8_desc(f); sort8_desc(g);
        merge8_desc(f, g);      // f = sorted top-8 of the 16
        merge8_desc(t0, f);
        // channel .y
        #pragma unroll
        for (int u = 0; u < 8; ++u) { f[u] = buf[u].y; g[u] = buf[u + 8].y; }
        sort8_desc(f); sort8_desc(g);
        merge8_desc(f, g);
        merge8_desc(t1, f);
    }

    // Store: layout [b][c][chunk][k]; one 32B evict_last store per channel.
    const int c0 = lane * 2;
    st_evl_32(g_partial + (((size_t)batch * C_DIM + c0) * CHUNKS + chunk) * K_TOP, t0);
    st_evl_32(g_partial + (((size_t)batch * C_DIM + c0 + 1) * CHUNKS + chunk) * K_TOP, t1);
}

// Pass 2 (R8 structure): warp = 4 (b,c) pairs, 8 lanes each. Lane owns 2
// chunks (64B, L2-resident), merges locally, then 3 shuffle-xor levels.
__global__ __launch_bounds__(256) void kmax_merge_kernel(float* __restrict__ out)
{
    const int warp_id = (blockIdx.x * blockDim.x + threadIdx.x) >> 5;
    const int lane = threadIdx.x & 31;
    const int sg = lane >> 3;                   // sub-group 0..3
    const int sl = lane & 7;                    // lane within sub-group
    const int gp = warp_id * 4 + sg;            // global (b,c) pair
    const int b = gp >> 8;                      // / C_DIM
    const int c = gp & (C_DIM - 1);

    // Pair gp occupies 128 floats; lane's 2 chunks = 16 consecutive floats.
    const float* pbase = g_partial + (size_t)gp * 128 + sl * 16;

    float v[8], g[8];
    ld_evf_32(pbase, v);        // chunk 2*sl (sorted 8)
    ld_evf_32(pbase + 8, g);    // chunk 2*sl+1 (sorted 8)
    merge8_desc(v, g);          // local merge, no shuffles

    #pragma unroll
    for (int d = 4; d >= 1; d >>= 1) {
        float h[8];
        #pragma unroll
        for (int i = 0; i < 8; ++i)
            h[i] = __shfl_xor_sync(0xFFFFFFFFu, v[i], d);
        merge8_desc(v, h);
    }

    out[((size_t)b * K_TOP + sl) * C_DIM + c] = v[sl];
}

extern "C" void kernel_launch(void* const* d_in, const int* in_sizes, int n_in,
                              void* d_out, int out_size) {
    const float2* x2 = (const float2*)d_in[0];
    float* out = (float*)d_out;

    kmax_partial_kernel<<<GRID1, 256>>>(x2);
    // 16384 pairs / 4 per warp = 4096 warps = 512 blocks x 8 warps.
    kmax_merge_kernel<<<512, 256>>>(out);
}